// round 1
// baseline (speedup 1.0000x reference)
#include <cuda_runtime.h>
#include <cstdint>

#define DV 128
#define TB 64      // tokens per block
#define JC 32      // j-chunk staged per step
#define NT 256     // threads per block
#define KSPLIT 2
#define STEPS ((DV / KSPLIT) * (DV / JC))   // 64 i-values * 4 j-chunks = 256

// shared memory layout (floats):
//   c_sh   : [2][JC][DV]      = 8192 floats  (offset 0)
//   m_sh   : [2][JC][TB]      = 4096 floats  (offset 8192)
//   arg_sh : [TB][DV+1]       = 8256 floats  (offset 12288)
//   func_sh: [TB][DV+1]       = 8256 floats  (offset 20544)
#define SM_C    0
#define SM_M    8192
#define SM_ARG  12288
#define SM_FUNC 20544
#define SM_FLOATS 28800
#define SM_BYTES (SM_FLOATS * 4)   // 115200

union U4 { float4 f4; unsigned long long u[2]; };
union U2 { unsigned long long u; float2 f; };

__device__ __forceinline__ unsigned long long ffma2(unsigned long long a,
                                                    unsigned long long b,
                                                    unsigned long long c) {
    unsigned long long d;
    asm("fma.rn.f32x2 %0, %1, %2, %3;" : "=l"(d) : "l"(a), "l"(b), "l"(c));
    return d;
}

__device__ __forceinline__ unsigned long long pack2(float x, float y) {
    unsigned long long d;
    asm("mov.b64 %0, {%1, %2};" : "=l"(d) : "f"(x), "f"(y));
    return d;
}

__global__ void __launch_bounds__(NT, 1)
cooc_kernel(const float* __restrict__ fa, const float* __restrict__ Cm,
            float* __restrict__ out) {
    extern __shared__ float sm[];
    float* c_sh   = sm + SM_C;
    float* m_sh   = sm + SM_M;
    float* arg_sh = sm + SM_ARG;
    float* func_sh= sm + SM_FUNC;

    const int tid  = threadIdx.x;
    const int lane = tid & 31;
    const int warp = tid >> 5;
    const int tok0 = blockIdx.x * TB;
    const int i0   = blockIdx.y * (DV / KSPLIT);

    const int tloc  = tid & 63;   // token index for m-staging
    const int jbase = tid >> 6;   // 0..3

    // ---- load func/arg tile into padded smem (one-time) ----
    for (int idx = tid; idx < TB * 2 * DV; idx += NT) {
        int t = idx >> 8;          // / 256
        int c = idx & 255;
        float v = fa[(size_t)(tok0 + t) * (2 * DV) + c];
        if (c < DV) func_sh[t * (DV + 1) + c] = v;
        else        arg_sh [t * (DV + 1) + (c - DV)] = v;
    }

    // ---- prefetch C slab for step 0 (independent of smem init) ----
    float4 cr[4];
    {
        const float4* src = (const float4*)(Cm + (size_t)i0 * DV * DV);
        #pragma unroll
        for (int k = 0; k < 4; k++) cr[k] = src[tid + k * NT];
    }
    __syncthreads();   // func/arg ready

    // ---- m-values for step 0 ----
    float mrv[8];
    {
        float fv = func_sh[tloc * (DV + 1) + i0];
        #pragma unroll
        for (int k = 0; k < 8; k++)
            mrv[k] = fv * arg_sh[tloc * (DV + 1) + (jbase + k * 4)];
    }
    // store step 0 into buffer 0
    {
        float4* cdst = (float4*)(c_sh);
        #pragma unroll
        for (int k = 0; k < 4; k++) cdst[tid + k * NT] = cr[k];
        #pragma unroll
        for (int k = 0; k < 8; k++) m_sh[(jbase + k * 4) * TB + tloc] = mrv[k];
    }
    __syncthreads();

    // ---- accumulators: acc[tp][zz] = f32x2 {token 2tp, token 2tp+1} at z = lane*4+zz
    unsigned long long acc[4][4];
    #pragma unroll
    for (int a = 0; a < 4; a++)
        #pragma unroll
        for (int b = 0; b < 4; b++) acc[a][b] = 0ull;

    int buf = 0;
    for (int s = 0; s + 1 < STEPS; s++) {
        // prefetch next step (global C + m from smem)
        const int sn = s + 1;
        const int i  = i0 + (sn >> 2);
        const int j0 = (sn & 3) * JC;
        {
            const float4* src =
                (const float4*)(Cm + (size_t)i * DV * DV + (size_t)j0 * DV);
            #pragma unroll
            for (int k = 0; k < 4; k++) cr[k] = src[tid + k * NT];
        }
        {
            float fv = func_sh[tloc * (DV + 1) + i];
            #pragma unroll
            for (int k = 0; k < 8; k++)
                mrv[k] = fv * arg_sh[tloc * (DV + 1) + j0 + (jbase + k * 4)];
        }

        // ---- compute on current buffer ----
        {
            const float* cb = c_sh + buf * (JC * DV);
            const float* mb = m_sh + buf * (JC * TB);
            #pragma unroll
            for (int jj = 0; jj < JC; jj++) {
                float4 c4 = ((const float4*)(cb + jj * DV))[lane];
                unsigned long long cz0 = pack2(c4.x, c4.x);
                unsigned long long cz1 = pack2(c4.y, c4.y);
                unsigned long long cz2 = pack2(c4.z, c4.z);
                unsigned long long cz3 = pack2(c4.w, c4.w);
                U4 ma, mbv;
                const float4* mrow = (const float4*)(mb + jj * TB + warp * 8);
                ma.f4  = mrow[0];   // tokens 0..3 of this warp's 8
                mbv.f4 = mrow[1];   // tokens 4..7
                acc[0][0] = ffma2(ma.u[0],  cz0, acc[0][0]);
                acc[0][1] = ffma2(ma.u[0],  cz1, acc[0][1]);
                acc[0][2] = ffma2(ma.u[0],  cz2, acc[0][2]);
                acc[0][3] = ffma2(ma.u[0],  cz3, acc[0][3]);
                acc[1][0] = ffma2(ma.u[1],  cz0, acc[1][0]);
                acc[1][1] = ffma2(ma.u[1],  cz1, acc[1][1]);
                acc[1][2] = ffma2(ma.u[1],  cz2, acc[1][2]);
                acc[1][3] = ffma2(ma.u[1],  cz3, acc[1][3]);
                acc[2][0] = ffma2(mbv.u[0], cz0, acc[2][0]);
                acc[2][1] = ffma2(mbv.u[0], cz1, acc[2][1]);
                acc[2][2] = ffma2(mbv.u[0], cz2, acc[2][2]);
                acc[2][3] = ffma2(mbv.u[0], cz3, acc[2][3]);
                acc[3][0] = ffma2(mbv.u[1], cz0, acc[3][0]);
                acc[3][1] = ffma2(mbv.u[1], cz1, acc[3][1]);
                acc[3][2] = ffma2(mbv.u[1], cz2, acc[3][2]);
                acc[3][3] = ffma2(mbv.u[1], cz3, acc[3][3]);
            }
        }

        // ---- store next step into the other buffer ----
        {
            const int nb = buf ^ 1;
            float4* cdst = (float4*)(c_sh + nb * (JC * DV));
            #pragma unroll
            for (int k = 0; k < 4; k++) cdst[tid + k * NT] = cr[k];
            float* mdst = m_sh + nb * (JC * TB);
            #pragma unroll
            for (int k = 0; k < 8; k++) mdst[(jbase + k * 4) * TB + tloc] = mrv[k];
        }
        __syncthreads();
        buf ^= 1;
    }

    // ---- final step compute ----
    {
        const float* cb = c_sh + buf * (JC * DV);
        const float* mb = m_sh + buf * (JC * TB);
        #pragma unroll
        for (int jj = 0; jj < JC; jj++) {
            float4 c4 = ((const float4*)(cb + jj * DV))[lane];
            unsigned long long cz0 = pack2(c4.x, c4.x);
            unsigned long long cz1 = pack2(c4.y, c4.y);
            unsigned long long cz2 = pack2(c4.z, c4.z);
            unsigned long long cz3 = pack2(c4.w, c4.w);
            U4 ma, mbv;
            const float4* mrow = (const float4*)(mb + jj * TB + warp * 8);
            ma.f4  = mrow[0];
            mbv.f4 = mrow[1];
            acc[0][0] = ffma2(ma.u[0],  cz0, acc[0][0]);
            acc[0][1] = ffma2(ma.u[0],  cz1, acc[0][1]);
            acc[0][2] = ffma2(ma.u[0],  cz2, acc[0][2]);
            acc[0][3] = ffma2(ma.u[0],  cz3, acc[0][3]);
            acc[1][0] = ffma2(ma.u[1],  cz0, acc[1][0]);
            acc[1][1] = ffma2(ma.u[1],  cz1, acc[1][1]);
            acc[1][2] = ffma2(ma.u[1],  cz2, acc[1][2]);
            acc[1][3] = ffma2(ma.u[1],  cz3, acc[1][3]);
            acc[2][0] = ffma2(mbv.u[0], cz0, acc[2][0]);
            acc[2][1] = ffma2(mbv.u[0], cz1, acc[2][1]);
            acc[2][2] = ffma2(mbv.u[0], cz2, acc[2][2]);
            acc[2][3] = ffma2(mbv.u[0], cz3, acc[2][3]);
            acc[3][0] = ffma2(mbv.u[1], cz0, acc[3][0]);
            acc[3][1] = ffma2(mbv.u[1], cz1, acc[3][1]);
            acc[3][2] = ffma2(mbv.u[1], cz2, acc[3][2]);
            acc[3][3] = ffma2(mbv.u[1], cz3, acc[3][3]);
        }
    }

    // ---- epilogue: 2-way K-split accumulation (exactly 2 atomic adds per
    //      output over a zeroed buffer -> bit-deterministic) ----
    #pragma unroll
    for (int tp = 0; tp < 4; tp++) {
        int tg = tok0 + warp * 8 + tp * 2;
        float* o0 = out + (size_t)tg * DV + lane * 4;
        float* o1 = o0 + DV;
        #pragma unroll
        for (int zz = 0; zz < 4; zz++) {
            U2 a; a.u = acc[tp][zz];
            atomicAdd(o0 + zz, a.f.x);   // token tg
            atomicAdd(o1 + zz, a.f.y);   // token tg+1
        }
    }
}

extern "C" void kernel_launch(void* const* d_in, const int* in_sizes, int n_in,
                              void* d_out, int out_size) {
    const float* fa = (const float*)d_in[0];   // (4,1024,256)  = 1,048,576
    const float* Cm = (const float*)d_in[1];   // (128,128,128) = 2,097,152
    if (n_in >= 2 && in_sizes[0] > in_sizes[1]) {   // defensive order check
        const float* t = fa; fa = Cm; Cm = t;
    }
    float* out = (float*)d_out;

    cudaFuncSetAttribute(cooc_kernel,
                         cudaFuncAttributeMaxDynamicSharedMemorySize, SM_BYTES);

    // zero the output (poisoned by harness); K-split halves accumulate into it
    cudaMemsetAsync(d_out, 0, (size_t)out_size * sizeof(float));

    dim3 grid(4096 / TB, KSPLIT);   // (64, 2) = 128 blocks, one full wave
    cooc_kernel<<<grid, NT, SM_BYTES>>>(fa, Cm, out);
}

// round 3
// speedup vs baseline: 2.6403x; 2.6403x over previous
#include <cuda_runtime.h>
#include <cstdint>

#define DV 128
#define NT 512
#define KSPLIT 4
#define IPC (DV / KSPLIT)      // 32 i-values per CTA

// smem word-offsets
#define SLAB_STRIDE 136                         // words per j-row (128 + 8 pad)
#define SLAB_WORDS  (DV * SLAB_STRIDE)          // 17408
#define OFF_SLAB0   0
#define OFF_SLAB1   SLAB_WORDS
#define OFF_ARG     (2 * SLAB_WORDS)            // 34816, stride 132
#define ARG_STRIDE  132
#define OFF_FUNC    (OFF_ARG + 128 * ARG_STRIDE) // 51712, stride 33
#define FUNC_STRIDE 33
#define SM_WORDS    (OFF_FUNC + 128 * FUNC_STRIDE) // 55936
#define SM_BYTES    (SM_WORDS * 4)              // 223744

__device__ __forceinline__ uint32_t smem_u32(const void* p) {
    uint32_t a;
    asm("{ .reg .u64 t; cvta.to.shared.u64 t, %1; cvt.u32.u64 %0, t; }"
        : "=r"(a) : "l"(p));
    return a;
}
__device__ __forceinline__ uint32_t rna_tf32(float x) {
    uint32_t r;
    asm("cvt.rna.tf32.f32 %0, %1;" : "=r"(r) : "f"(x));
    return r;
}
__device__ __forceinline__ void cp16(uint32_t dst, const void* src) {
    asm volatile("cp.async.cg.shared.global [%0], [%1], 16;"
                 :: "r"(dst), "l"(src) : "memory");
}
#define CP_COMMIT() asm volatile("cp.async.commit_group;" ::: "memory")
#define CP_WAIT(n)  asm volatile("cp.async.wait_group %0;" :: "n"(n) : "memory")

__device__ __forceinline__ void mma_tf32(float* c, const uint32_t* a,
                                         uint32_t b0, uint32_t b1) {
    asm volatile(
        "mma.sync.aligned.m16n8k8.row.col.f32.tf32.tf32.f32 "
        "{%0,%1,%2,%3}, {%4,%5,%6,%7}, {%8,%9}, {%0,%1,%2,%3};"
        : "+f"(c[0]), "+f"(c[1]), "+f"(c[2]), "+f"(c[3])
        : "r"(a[0]), "r"(a[1]), "r"(a[2]), "r"(a[3]), "r"(b0), "r"(b1));
}

__global__ void __launch_bounds__(NT, 1)
cooc_mma(const float* __restrict__ fa, const float* __restrict__ Cm,
         float* __restrict__ out) {
    extern __shared__ float sm[];
    const int tid  = threadIdx.x;
    const int warp = tid >> 5, lane = tid & 31;
    const int g = lane >> 2, q = lane & 3;
    const int mbase = (warp >> 2) * 32;   // warp-row tile
    const int nbase = (warp & 3) * 32;    // warp-col tile
    const int tok0 = blockIdx.x * 128;
    const int i0   = blockIdx.y * IPC;

    float* arg_sh  = sm + OFF_ARG;
    float* func_sh = sm + OFF_FUNC;

    // ---- stage arg [128 tok][128 j] (stride 132) and func [128 tok][32 i] ----
    for (int idx = tid; idx < 128 * 128; idx += NT) {
        int t = idx >> 7, c = idx & 127;
        arg_sh[t * ARG_STRIDE + c] = fa[(size_t)(tok0 + t) * 256 + DV + c];
    }
    for (int idx = tid; idx < 128 * IPC; idx += NT) {
        int t = idx >> 5, ii = idx & 31;
        func_sh[t * FUNC_STRIDE + ii] = fa[(size_t)(tok0 + t) * 256 + i0 + ii];
    }

    // ---- cp.async slab stager: C[i][j 0..127][z 0..127] -> slab (row stride 136)
    const uint32_t sb = smem_u32(sm);
    auto stage = [&](int i_rel, int buf) {
        const float* src = Cm + ((size_t)(i0 + i_rel) << 14);
        uint32_t dstb = sb + (buf ? OFF_SLAB1 : OFF_SLAB0) * 4;
        #pragma unroll
        for (int k = 0; k < 8; k++) {
            int c = tid + k * NT;          // 16B chunk id, 0..4095
            int row = c >> 5, col = c & 31;
            cp16(dstb + (row * SLAB_STRIDE + col * 4) * 4,
                 src + row * DV + col * 4);
        }
    };

    stage(0, 0);
    CP_COMMIT();

    float acc[2][4][4];
    #pragma unroll
    for (int mt = 0; mt < 2; mt++)
        #pragma unroll
        for (int nt = 0; nt < 4; nt++)
            #pragma unroll
            for (int k = 0; k < 4; k++) acc[mt][nt][k] = 0.f;

    for (int i = 0; i < IPC; i++) {
        if (i + 1 < IPC) { stage(i + 1, (i + 1) & 1); CP_COMMIT(); }
        if (i + 1 < IPC) CP_WAIT(1); else CP_WAIT(0);
        __syncthreads();

        const float* slab = sm + ((i & 1) ? OFF_SLAB1 : OFF_SLAB0);

        // func values for this i: rows mbase + g + 8s
        float fr[4];
        #pragma unroll
        for (int s = 0; s < 4; s++)
            fr[s] = func_sh[(mbase + g + 8 * s) * FUNC_STRIDE + i];

        #pragma unroll 4
        for (int jc = 0; jc < 16; jc++) {
            const int jb = jc * 8;
            // A fragments: M[t, j] = func[t,i] * arg[t,j], tf32-rounded
            uint32_t a[2][4];
            #pragma unroll
            for (int s = 0; s < 4; s++) {
                const float* ap = arg_sh + (mbase + g + 8 * s) * ARG_STRIDE + jb + q;
                float lo = ap[0], hi = ap[4];
                a[s >> 1][(s & 1) ? 1 : 0] = rna_tf32(fr[s] * lo);
                a[s >> 1][(s & 1) ? 3 : 2] = rna_tf32(fr[s] * hi);
            }
            // B fragments + mma
            #pragma unroll
            for (int nt = 0; nt < 4; nt++) {
                const float* bp = slab + (jb + q) * SLAB_STRIDE + nbase + nt * 8 + g;
                uint32_t b0 = rna_tf32(bp[0]);
                uint32_t b1 = rna_tf32(bp[4 * SLAB_STRIDE]);
                mma_tf32(acc[0][nt], a[0], b0, b1);
                mma_tf32(acc[1][nt], a[1], b0, b1);
            }
        }
        __syncthreads();
    }

    // ---- epilogue: KSPLIT partial sums via atomicAdd over zeroed output ----
    #pragma unroll
    for (int mt = 0; mt < 2; mt++) {
        int r0 = tok0 + mbase + mt * 16 + g;
        #pragma unroll
        for (int nt = 0; nt < 4; nt++) {
            int col = nbase + nt * 8 + 2 * q;
            float* p0 = out + (size_t)r0 * DV + col;
            atomicAdd(p0,          acc[mt][nt][0]);
            atomicAdd(p0 + 1,      acc[mt][nt][1]);
            atomicAdd(p0 + 8 * DV,     acc[mt][nt][2]);
            atomicAdd(p0 + 8 * DV + 1, acc[mt][nt][3]);
        }
    }
}

extern "C" void kernel_launch(void* const* d_in, const int* in_sizes, int n_in,
                              void* d_out, int out_size) {
    const float* fa = (const float*)d_in[0];   // (4,1024,256)
    const float* Cm = (const float*)d_in[1];   // (128,128,128)
    if (n_in >= 2 && in_sizes[0] > in_sizes[1]) {
        const float* t = fa; fa = Cm; Cm = t;
    }
    float* out = (float*)d_out;

    cudaFuncSetAttribute(cooc_mma, cudaFuncAttributeMaxDynamicSharedMemorySize,
                         SM_BYTES);
    cudaMemsetAsync(d_out, 0, (size_t)out_size * sizeof(float));
    cooc_mma<<<dim3(4096 / 128, KSPLIT), NT, SM_BYTES>>>(fa, Cm, out);
}

// round 4
// speedup vs baseline: 3.0065x; 1.1387x over previous
#include <cuda_runtime.h>
#include <cstdint>

#define DV 128
#define NT 512
#define KSPLIT 4
#define IPC (DV / KSPLIT)      // 32 i-values per CTA

// smem word-offsets
#define SLAB_STRIDE 136                         // words per j-row (128 + 8 pad)
#define SLAB_WORDS  (DV * SLAB_STRIDE)          // 17408
#define OFF_SLAB0   0
#define OFF_SLAB1   SLAB_WORDS
#define OFF_ARG     (2 * SLAB_WORDS)            // 34816, stride 132
#define ARG_STRIDE  132
#define OFF_FUNC    (OFF_ARG + 128 * ARG_STRIDE) // 51712, stride 33
#define FUNC_STRIDE 33
#define SM_WORDS    (OFF_FUNC + 128 * FUNC_STRIDE) // 55936
#define SM_BYTES    (SM_WORDS * 4)              // 223744

// C pre-rounded to tf32 (same [i][j][z] layout)
__device__ float g_CR[DV * DV * DV];

__device__ __forceinline__ uint32_t smem_u32(const void* p) {
    uint32_t a;
    asm("{ .reg .u64 t; cvta.to.shared.u64 t, %1; cvt.u32.u64 %0, t; }"
        : "=r"(a) : "l"(p));
    return a;
}
__device__ __forceinline__ uint32_t rna_tf32(float x) {
    uint32_t r;
    asm("cvt.rna.tf32.f32 %0, %1;" : "=r"(r) : "f"(x));
    return r;
}
__device__ __forceinline__ void cp16(uint32_t dst, const void* src) {
    asm volatile("cp.async.cg.shared.global [%0], [%1], 16;"
                 :: "r"(dst), "l"(src) : "memory");
}
#define CP_COMMIT() asm volatile("cp.async.commit_group;" ::: "memory")
#define CP_WAIT(n)  asm volatile("cp.async.wait_group %0;" :: "n"(n) : "memory")

__device__ __forceinline__ void mma_tf32(float* c, const uint32_t* a,
                                         uint32_t b0, uint32_t b1) {
    asm volatile(
        "mma.sync.aligned.m16n8k8.row.col.f32.tf32.tf32.f32 "
        "{%0,%1,%2,%3}, {%4,%5,%6,%7}, {%8,%9}, {%0,%1,%2,%3};"
        : "+f"(c[0]), "+f"(c[1]), "+f"(c[2]), "+f"(c[3])
        : "r"(a[0]), "r"(a[1]), "r"(a[2]), "r"(a[3]), "r"(b0), "r"(b1));
}

// ---- elementwise tf32 pre-round of C ----
__global__ void __launch_bounds__(256) round_c(const float4* __restrict__ C) {
    size_t idx = (size_t)blockIdx.x * 256 + threadIdx.x;   // 524288 float4s
    float4 v = C[idx];
    float4 r;
    r.x = __uint_as_float(rna_tf32(v.x));
    r.y = __uint_as_float(rna_tf32(v.y));
    r.z = __uint_as_float(rna_tf32(v.z));
    r.w = __uint_as_float(rna_tf32(v.w));
    ((float4*)g_CR)[idx] = r;
}

__global__ void __launch_bounds__(NT, 1)
cooc_mma(const float* __restrict__ fa, float* __restrict__ out) {
    extern __shared__ float sm[];
    const int tid  = threadIdx.x;
    const int warp = tid >> 5, lane = tid & 31;
    const int g = lane >> 2, q = lane & 3;
    const int wid = warp & 7;            // output tile id (4 rows x 2 cols)
    const int kp  = warp >> 3;           // 0/1: jc parity handled by this warp
    const int mbase = (wid >> 1) * 32;   // warp-row tile (32 tokens)
    const int nbase = (wid & 1) * 64;    // warp-col tile (64 z)
    const int tok0 = blockIdx.x * 128;
    const int i0   = blockIdx.y * IPC;

    float* arg_sh  = sm + OFF_ARG;
    float* func_sh = sm + OFF_FUNC;

    // ---- stage arg [128 tok][128 j] (stride 132) and func [128 tok][32 i] ----
    for (int idx = tid; idx < 128 * 128; idx += NT) {
        int t = idx >> 7, c = idx & 127;
        arg_sh[t * ARG_STRIDE + c] = fa[(size_t)(tok0 + t) * 256 + DV + c];
    }
    for (int idx = tid; idx < 128 * IPC; idx += NT) {
        int t = idx >> 5, ii = idx & 31;
        func_sh[t * FUNC_STRIDE + ii] = fa[(size_t)(tok0 + t) * 256 + i0 + ii];
    }

    // ---- cp.async slab stager: CR[i][j 0..127][z 0..127] -> slab (row stride 136)
    const uint32_t sb = smem_u32(sm);
    auto stage = [&](int i_rel, int buf) {
        const float* src = g_CR + ((size_t)(i0 + i_rel) << 14);
        uint32_t dstb = sb + (buf ? OFF_SLAB1 : OFF_SLAB0) * 4;
        #pragma unroll
        for (int k = 0; k < 8; k++) {
            int c = tid + k * NT;          // 16B chunk id, 0..4095
            int row = c >> 5, col = c & 31;
            cp16(dstb + (row * SLAB_STRIDE + col * 4) * 4,
                 src + row * DV + col * 4);
        }
    };

    stage(0, 0);
    CP_COMMIT();

    float acc[2][8][4];
    #pragma unroll
    for (int mt = 0; mt < 2; mt++)
        #pragma unroll
        for (int nt = 0; nt < 8; nt++)
            #pragma unroll
            for (int k = 0; k < 4; k++) acc[mt][nt][k] = 0.f;

    for (int i = 0; i < IPC; i++) {
        if (i + 1 < IPC) { stage(i + 1, (i + 1) & 1); CP_COMMIT(); }
        if (i + 1 < IPC) CP_WAIT(1); else CP_WAIT(0);
        __syncthreads();

        const float* slab = sm + ((i & 1) ? OFF_SLAB1 : OFF_SLAB0);

        // func values for this i: rows mbase + g + 8s
        float fr[4];
        #pragma unroll
        for (int s = 0; s < 4; s++)
            fr[s] = func_sh[(mbase + g + 8 * s) * FUNC_STRIDE + i];

        // this warp handles jc = kp, kp+2, ... (8 of 16 chunks)
        #pragma unroll 4
        for (int jc = kp; jc < 16; jc += 2) {
            const int jb = jc * 8;
            // A fragments: M[t, j] = func[t,i] * arg[t,j], tf32-rounded
            uint32_t a[2][4];
            #pragma unroll
            for (int s = 0; s < 4; s++) {
                const float* ap = arg_sh + (mbase + g + 8 * s) * ARG_STRIDE + jb + q;
                float lo = ap[0], hi = ap[4];
                a[s >> 1][(s & 1) ? 1 : 0] = rna_tf32(fr[s] * lo);
                a[s >> 1][(s & 1) ? 3 : 2] = rna_tf32(fr[s] * hi);
            }
            // B fragments (pre-rounded tf32, no cvt) + mma
            #pragma unroll
            for (int nt = 0; nt < 8; nt++) {
                const float* bp = slab + (jb + q) * SLAB_STRIDE + nbase + nt * 8 + g;
                uint32_t b0 = __float_as_uint(bp[0]);
                uint32_t b1 = __float_as_uint(bp[4 * SLAB_STRIDE]);
                mma_tf32(acc[0][nt], a[0], b0, b1);
                mma_tf32(acc[1][nt], a[1], b0, b1);
            }
        }
        __syncthreads();
    }

    // ---- epilogue: KSPLIT*2 partial sums via atomicAdd over zeroed output ----
    #pragma unroll
    for (int mt = 0; mt < 2; mt++) {
        int r0 = tok0 + mbase + mt * 16 + g;
        #pragma unroll
        for (int nt = 0; nt < 8; nt++) {
            int col = nbase + nt * 8 + 2 * q;
            float* p0 = out + (size_t)r0 * DV + col;
            atomicAdd(p0,              acc[mt][nt][0]);
            atomicAdd(p0 + 1,          acc[mt][nt][1]);
            atomicAdd(p0 + 8 * DV,     acc[mt][nt][2]);
            atomicAdd(p0 + 8 * DV + 1, acc[mt][nt][3]);
        }
    }
}

extern "C" void kernel_launch(void* const* d_in, const int* in_sizes, int n_in,
                              void* d_out, int out_size) {
    const float* fa = (const float*)d_in[0];   // (4,1024,256)
    const float* Cm = (const float*)d_in[1];   // (128,128,128)
    if (n_in >= 2 && in_sizes[0] > in_sizes[1]) {
        const float* t = fa; fa = Cm; Cm = t;
    }
    float* out = (float*)d_out;

    cudaFuncSetAttribute(cooc_mma, cudaFuncAttributeMaxDynamicSharedMemorySize,
                         SM_BYTES);
    cudaMemsetAsync(d_out, 0, (size_t)out_size * sizeof(float));
    round_c<<<2048, 256>>>((const float4*)Cm);
    cooc_mma<<<dim3(4096 / 128, KSPLIT), NT, SM_BYTES>>>(fa, out);
}

// round 5
// speedup vs baseline: 3.1594x; 1.0509x over previous
#include <cuda_runtime.h>
#include <cstdint>

#define DV 128
#define NT 256
#define KSPLIT 4
#define IPC (DV / KSPLIT)      // 32 i-values per CTA

// smem word-offsets
#define SLAB_STRIDE 136                          // words per j-row (128 + 8 pad)
#define SLAB_WORDS  (DV * SLAB_STRIDE)           // 17408
#define OFF_SLAB0   0
#define OFF_SLAB1   SLAB_WORDS
#define OFF_ARG     (2 * SLAB_WORDS)             // 34816, stride 132
#define ARG_STRIDE  132
#define OFF_FUNC    (OFF_ARG + 128 * ARG_STRIDE) // 51712
#define FUNC_STRIDE 36
#define SM_WORDS    (OFF_FUNC + 128 * FUNC_STRIDE) // 56320
#define SM_BYTES    (SM_WORDS * 4)               // 225280

// C pre-rounded to tf32 (same [i][j][z] layout)
__device__ float g_CR[DV * DV * DV];

__device__ __forceinline__ uint32_t smem_u32(const void* p) {
    uint32_t a;
    asm("{ .reg .u64 t; cvta.to.shared.u64 t, %1; cvt.u32.u64 %0, t; }"
        : "=r"(a) : "l"(p));
    return a;
}
__device__ __forceinline__ uint32_t rna_tf32(float x) {
    uint32_t r;
    asm("cvt.rna.tf32.f32 %0, %1;" : "=r"(r) : "f"(x));
    return r;
}
__device__ __forceinline__ void cp16(uint32_t dst, const void* src) {
    asm volatile("cp.async.cg.shared.global [%0], [%1], 16;"
                 :: "r"(dst), "l"(src) : "memory");
}
#define CP_COMMIT() asm volatile("cp.async.commit_group;" ::: "memory")
#define CP_WAIT(n)  asm volatile("cp.async.wait_group %0;" :: "n"(n) : "memory")

__device__ __forceinline__ void mma_tf32(float* c, const uint32_t* a,
                                         uint32_t b0, uint32_t b1) {
    asm volatile(
        "mma.sync.aligned.m16n8k8.row.col.f32.tf32.tf32.f32 "
        "{%0,%1,%2,%3}, {%4,%5,%6,%7}, {%8,%9}, {%0,%1,%2,%3};"
        : "+f"(c[0]), "+f"(c[1]), "+f"(c[2]), "+f"(c[3])
        : "r"(a[0]), "r"(a[1]), "r"(a[2]), "r"(a[3]), "r"(b0), "r"(b1));
}

// ---- elementwise tf32 pre-round of C ----
__global__ void __launch_bounds__(256) round_c(const float4* __restrict__ C) {
    size_t idx = (size_t)blockIdx.x * 256 + threadIdx.x;   // 524288 float4s
    float4 v = C[idx];
    float4 r;
    r.x = __uint_as_float(rna_tf32(v.x));
    r.y = __uint_as_float(rna_tf32(v.y));
    r.z = __uint_as_float(rna_tf32(v.z));
    r.w = __uint_as_float(rna_tf32(v.w));
    ((float4*)g_CR)[idx] = r;
}

__global__ void __launch_bounds__(NT, 1)
cooc_mma(const float* __restrict__ fa, float* __restrict__ out) {
    extern __shared__ float sm[];
    const int tid  = threadIdx.x;
    const int warp = tid >> 5, lane = tid & 31;
    const int g = lane >> 2, q = lane & 3;
    const int mbase = (warp >> 1) * 32;   // warp-row tile (32 tokens)
    const int nbase = (warp & 1) * 64;    // warp-col tile (64 z)
    const int tok0 = blockIdx.x * 128;
    const int i0   = blockIdx.y * IPC;

    float* arg_sh  = sm + OFF_ARG;
    float* func_sh = sm + OFF_FUNC;

    // ---- stage arg [128 tok][128 j] (stride 132) and func [128 tok][32 i] ----
    for (int idx = tid; idx < 128 * 32; idx += NT) {     // float4 granularity
        int t = idx >> 5, c = idx & 31;
        float4 v = *(const float4*)(fa + (size_t)(tok0 + t) * 256 + DV + c * 4);
        *(float4*)(arg_sh + t * ARG_STRIDE + c * 4) = v;
    }
    for (int idx = tid; idx < 128 * 8; idx += NT) {      // float4 granularity
        int t = idx >> 3, c = idx & 7;
        float4 v = *(const float4*)(fa + (size_t)(tok0 + t) * 256 + i0 + c * 4);
        func_sh[t * FUNC_STRIDE + c * 4 + 0] = v.x;
        func_sh[t * FUNC_STRIDE + c * 4 + 1] = v.y;
        func_sh[t * FUNC_STRIDE + c * 4 + 2] = v.z;
        func_sh[t * FUNC_STRIDE + c * 4 + 3] = v.w;
    }

    // ---- cp.async slab stager: CR[i][j 0..127][z 0..127] -> slab (stride 136)
    const uint32_t sb = smem_u32(sm);
    auto stage = [&](int i_rel, int buf) {
        const float* src = g_CR + ((size_t)(i0 + i_rel) << 14);
        uint32_t dstb = sb + (buf ? OFF_SLAB1 : OFF_SLAB0) * 4;
        #pragma unroll
        for (int k = 0; k < 16; k++) {
            int c = tid + k * NT;          // 16B chunk id, 0..4095
            int row = c >> 5, col = c & 31;
            cp16(dstb + (row * SLAB_STRIDE + col * 4) * 4,
                 src + row * DV + col * 4);
        }
    };

    stage(0, 0);
    CP_COMMIT();

    float acc[2][8][4];
    #pragma unroll
    for (int mt = 0; mt < 2; mt++)
        #pragma unroll
        for (int nt = 0; nt < 8; nt++)
            #pragma unroll
            for (int k = 0; k < 4; k++) acc[mt][nt][k] = 0.f;

    uint32_t a[2][2][4];     // [buf][mt][frag]
    uint32_t b[2][8][2];     // [buf][nt][frag]

    for (int i = 0; i < IPC; i++) {
        if (i + 1 < IPC) { stage(i + 1, (i + 1) & 1); CP_COMMIT(); }
        if (i + 1 < IPC) CP_WAIT(1); else CP_WAIT(0);
        __syncthreads();

        const float* slab = sm + ((i & 1) ? OFF_SLAB1 : OFF_SLAB0);

        // func values for this i: rows mbase + g + 8s
        float fr[4];
        #pragma unroll
        for (int s = 0; s < 4; s++)
            fr[s] = func_sh[(mbase + g + 8 * s) * FUNC_STRIDE + i];

        // fragment loader for one jc into buffer fb
        auto load_frags = [&](int jc, int fb) {
            const int jb = jc * 8;
            #pragma unroll
            for (int nt = 0; nt < 8; nt++) {
                const float* bp = slab + (jb + q) * SLAB_STRIDE + nbase + nt * 8 + g;
                b[fb][nt][0] = __float_as_uint(bp[0]);
                b[fb][nt][1] = __float_as_uint(bp[4 * SLAB_STRIDE]);
            }
            #pragma unroll
            for (int s = 0; s < 4; s++) {
                const float* ap = arg_sh + (mbase + g + 8 * s) * ARG_STRIDE + jb + q;
                float lo = ap[0], hi = ap[4];
                a[fb][s >> 1][(s & 1) ? 1 : 0] = rna_tf32(fr[s] * lo);
                a[fb][s >> 1][(s & 1) ? 3 : 2] = rna_tf32(fr[s] * hi);
            }
        };

        load_frags(0, 0);
        #pragma unroll
        for (int jc = 0; jc < 16; jc++) {
            const int cur = jc & 1, nxt = cur ^ 1;
            if (jc < 15) load_frags(jc + 1, nxt);
            #pragma unroll
            for (int nt = 0; nt < 8; nt++) {
                mma_tf32(acc[0][nt], a[cur][0], b[cur][nt][0], b[cur][nt][1]);
                mma_tf32(acc[1][nt], a[cur][1], b[cur][nt][0], b[cur][nt][1]);
            }
        }
        __syncthreads();
    }

    // ---- epilogue: KSPLIT partial sums via atomicAdd over zeroed output ----
    #pragma unroll
    for (int mt = 0; mt < 2; mt++) {
        int r0 = tok0 + mbase + mt * 16 + g;
        #pragma unroll
        for (int nt = 0; nt < 8; nt++) {
            int col = nbase + nt * 8 + 2 * q;
            float* p0 = out + (size_t)r0 * DV + col;
            atomicAdd(p0,              acc[mt][nt][0]);
            atomicAdd(p0 + 1,          acc[mt][nt][1]);
            atomicAdd(p0 + 8 * DV,     acc[mt][nt][2]);
            atomicAdd(p0 + 8 * DV + 1, acc[mt][nt][3]);
        }
    }
}

extern "C" void kernel_launch(void* const* d_in, const int* in_sizes, int n_in,
                              void* d_out, int out_size) {
    const float* fa = (const float*)d_in[0];   // (4,1024,256)
    const float* Cm = (const float*)d_in[1];   // (128,128,128)
    if (n_in >= 2 && in_sizes[0] > in_sizes[1]) {
        const float* t = fa; fa = Cm; Cm = t;
    }
    float* out = (float*)d_out;

    cudaFuncSetAttribute(cooc_mma, cudaFuncAttributeMaxDynamicSharedMemorySize,
                         SM_BYTES);
    cudaMemsetAsync(d_out, 0, (size_t)out_size * sizeof(float));
    round_c<<<2048, 256>>>((const float4*)Cm);
    cooc_mma<<<dim3(4096 / 128, KSPLIT), NT, SM_BYTES>>>(fa, out);
}

// round 6
// speedup vs baseline: 4.9673x; 1.5722x over previous
#include <cuda_runtime.h>
#include <cuda_fp16.h>
#include <cstdint>

#define DV 128
#define NT 512
#define KSPLIT 4
#define IPC (DV / KSPLIT)      // 32 i-values per CTA

// smem word-offsets
#define SLAB_STRIDE 136                     // words (half2) per j2-row: 128 + 8 pad
#define SLAB_WORDS  (64 * SLAB_STRIDE)      // 8704 words per buffer
#define OFF_SLAB0   0
#define OFF_SLAB1   SLAB_WORDS              // 8704
#define OFF_ARG     (2 * SLAB_WORDS)        // 17408, f32, stride 136
#define ARG_STRIDE  136
#define OFF_FUNC    (OFF_ARG + 128 * ARG_STRIDE)  // 34816, f32, stride 36
#define FUNC_STRIDE 36
#define SM_WORDS    (OFF_FUNC + 128 * FUNC_STRIDE) // 39424
#define SM_BYTES    (SM_WORDS * 4)          // 157696

// C packed to fp16 j-pair-interleaved: g_CH[i][j2][z] = half2(C[i][2j2][z], C[i][2j2+1][z])
__device__ uint32_t g_CH[DV * 64 * DV];

__device__ __forceinline__ uint32_t smem_u32(const void* p) {
    uint32_t a;
    asm("{ .reg .u64 t; cvta.to.shared.u64 t, %1; cvt.u32.u64 %0, t; }"
        : "=r"(a) : "l"(p));
    return a;
}
// pack (lo -> low f16, hi -> high f16)
__device__ __forceinline__ uint32_t pack_f16x2(float hi, float lo) {
    uint32_t r;
    asm("cvt.rn.f16x2.f32 %0, %1, %2;" : "=r"(r) : "f"(hi), "f"(lo));
    return r;
}
__device__ __forceinline__ void cp16(uint32_t dst, const void* src) {
    asm volatile("cp.async.cg.shared.global [%0], [%1], 16;"
                 :: "r"(dst), "l"(src) : "memory");
}
#define CP_COMMIT() asm volatile("cp.async.commit_group;" ::: "memory")
#define CP_WAIT(n)  asm volatile("cp.async.wait_group %0;" :: "n"(n) : "memory")

__device__ __forceinline__ void mma_f16(float* c, const uint32_t* a,
                                        uint32_t b0, uint32_t b1) {
    asm volatile(
        "mma.sync.aligned.m16n8k16.row.col.f32.f16.f16.f32 "
        "{%0,%1,%2,%3}, {%4,%5,%6,%7}, {%8,%9}, {%0,%1,%2,%3};"
        : "+f"(c[0]), "+f"(c[1]), "+f"(c[2]), "+f"(c[3])
        : "r"(a[0]), "r"(a[1]), "r"(a[2]), "r"(a[3]), "r"(b0), "r"(b1));
}

// ---- pack C -> fp16 pair-interleaved ----
__global__ void __launch_bounds__(256) pack_c(const float* __restrict__ C) {
    size_t idx = (size_t)blockIdx.x * 256 + threadIdx.x;   // 1,048,576
    int z  = (int)(idx & 127);
    int j2 = (int)((idx >> 7) & 63);
    int i  = (int)(idx >> 13);
    float v0 = C[((size_t)i * DV + 2 * j2) * DV + z];
    float v1 = C[((size_t)i * DV + 2 * j2 + 1) * DV + z];
    g_CH[idx] = pack_f16x2(v1, v0);
}

__global__ void __launch_bounds__(NT, 1)
cooc_mma(const float* __restrict__ fa, float* __restrict__ out) {
    extern __shared__ float sm[];
    const int tid  = threadIdx.x;
    const int warp = tid >> 5, lane = tid & 31;
    const int g = lane >> 2, q = lane & 3;
    const int wid = warp & 7;            // output tile id (4 rows x 2 cols)
    const int kp  = warp >> 3;           // 0/1: k-chunk parity for this warp
    const int mbase = (wid >> 1) * 32;   // warp-row tile (32 tokens)
    const int nbase = (wid & 1) * 64;    // warp-col tile (64 z)
    const int tok0 = blockIdx.x * 128;
    const int i0   = blockIdx.y * IPC;

    float* arg_sh  = sm + OFF_ARG;
    float* func_sh = sm + OFF_FUNC;

    // ---- stage arg [128 tok][128 j] f32 (stride 136) and func [128 tok][32 i]
    for (int idx = tid; idx < 128 * 32; idx += NT) {     // float4 granularity
        int t = idx >> 5, c = idx & 31;
        float4 v = *(const float4*)(fa + (size_t)(tok0 + t) * 256 + DV + c * 4);
        *(float4*)(arg_sh + t * ARG_STRIDE + c * 4) = v;
    }
    for (int idx = tid; idx < 128 * 8; idx += NT) {      // float4 granularity
        int t = idx >> 3, c = idx & 7;
        float4 v = *(const float4*)(fa + (size_t)(tok0 + t) * 256 + i0 + c * 4);
        func_sh[t * FUNC_STRIDE + c * 4 + 0] = v.x;
        func_sh[t * FUNC_STRIDE + c * 4 + 1] = v.y;
        func_sh[t * FUNC_STRIDE + c * 4 + 2] = v.z;
        func_sh[t * FUNC_STRIDE + c * 4 + 3] = v.w;
    }

    // ---- cp.async slab stager: g_CH[i][64 j2][128 z] -> slab (stride 136 words)
    const uint32_t sb = smem_u32(sm);
    auto stage = [&](int i_rel, int buf) {
        const uint32_t* src = g_CH + ((size_t)(i0 + i_rel) << 13);
        uint32_t dstb = sb + (buf ? OFF_SLAB1 : OFF_SLAB0) * 4;
        #pragma unroll
        for (int k = 0; k < 4; k++) {
            int c = tid + k * NT;          // 16B chunk id, 0..2047
            int row = c >> 5, col = c & 31;
            cp16(dstb + (row * SLAB_STRIDE + col * 4) * 4,
                 src + row * 128 + col * 4);
        }
    };

    stage(0, 0);
    CP_COMMIT();

    float acc[2][8][4];
    #pragma unroll
    for (int mt = 0; mt < 2; mt++)
        #pragma unroll
        for (int nt = 0; nt < 8; nt++)
            #pragma unroll
            for (int k = 0; k < 4; k++) acc[mt][nt][k] = 0.f;

    for (int i = 0; i < IPC; i++) {
        if (i + 1 < IPC) { stage(i + 1, (i + 1) & 1); CP_COMMIT(); }
        if (i + 1 < IPC) CP_WAIT(1); else CP_WAIT(0);
        __syncthreads();

        const uint32_t* slab =
            (const uint32_t*)(sm + ((i & 1) ? OFF_SLAB1 : OFF_SLAB0));

        // func values for this i: rows mbase + g + 8s
        float fr[4];
        #pragma unroll
        for (int s = 0; s < 4; s++)
            fr[s] = func_sh[(mbase + g + 8 * s) * FUNC_STRIDE + i];

        // this warp handles k16-chunks c = kp, kp+2, kp+4, kp+6
        #pragma unroll
        for (int c = kp; c < 8; c += 2) {
            const int jb = c * 16;      // j base of this k16 chunk
            const int c8 = c * 8;       // j2 base
            // A fragments: fp16(func[t,i] * arg[t,j])
            uint32_t a[2][4];
            #pragma unroll
            for (int s = 0; s < 4; s++) {
                const float* ap =
                    arg_sh + (mbase + g + 8 * s) * ARG_STRIDE + jb + 2 * q;
                float2 lo = *(const float2*)ap;          // k = 2q, 2q+1
                float2 hi = *(const float2*)(ap + 8);    // k = 2q+8, 2q+9
                uint32_t alo = pack_f16x2(fr[s] * lo.y, fr[s] * lo.x);
                uint32_t ahi = pack_f16x2(fr[s] * hi.y, fr[s] * hi.x);
                a[s >> 1][(s & 1) ? 1 : 0] = alo;
                a[s >> 1][(s & 1) ? 3 : 2] = ahi;
            }
            // B fragments (pre-packed fp16 pairs) + mma
            #pragma unroll
            for (int nt = 0; nt < 8; nt++) {
                const uint32_t* bp =
                    slab + (c8 + q) * SLAB_STRIDE + nbase + nt * 8 + g;
                uint32_t b0 = bp[0];
                uint32_t b1 = bp[4 * SLAB_STRIDE];
                mma_f16(acc[0][nt], a[0], b0, b1);
                mma_f16(acc[1][nt], a[1], b0, b1);
            }
        }
        __syncthreads();
    }

    // ---- epilogue: KSPLIT*2 deterministic partials via atomicAdd over zeroed out
    #pragma unroll
    for (int mt = 0; mt < 2; mt++) {
        int r0 = tok0 + mbase + mt * 16 + g;
        #pragma unroll
        for (int nt = 0; nt < 8; nt++) {
            int col = nbase + nt * 8 + 2 * q;
            float* p0 = out + (size_t)r0 * DV + col;
            atomicAdd(p0,              acc[mt][nt][0]);
            atomicAdd(p0 + 1,          acc[mt][nt][1]);
            atomicAdd(p0 + 8 * DV,     acc[mt][nt][2]);
            atomicAdd(p0 + 8 * DV + 1, acc[mt][nt][3]);
        }
    }
}

extern "C" void kernel_launch(void* const* d_in, const int* in_sizes, int n_in,
                              void* d_out, int out_size) {
    const float* fa = (const float*)d_in[0];   // (4,1024,256)
    const float* Cm = (const float*)d_in[1];   // (128,128,128)
    if (n_in >= 2 && in_sizes[0] > in_sizes[1]) {
        const float* t = fa; fa = Cm; Cm = t;
    }
    float* out = (float*)d_out;

    cudaFuncSetAttribute(cooc_mma, cudaFuncAttributeMaxDynamicSharedMemorySize,
                         SM_BYTES);
    cudaMemsetAsync(d_out, 0, (size_t)out_size * sizeof(float));
    pack_c<<<4096, 256>>>(Cm);
    cooc_mma<<<dim3(4096 / 128, KSPLIT), NT, SM_BYTES>>>(fa, out);
}

// round 7
// speedup vs baseline: 5.7741x; 1.1624x over previous
#include <cuda_runtime.h>
#include <cuda_fp16.h>
#include <cstdint>

#define DV 128
#define NT 256
#define KSPLIT 4
#define IPC (DV / KSPLIT)      // 32 i-values per CTA

// smem word-offsets (32-bit words)
#define SLAB_STRIDE 136                     // words (half2) per j2-row: 128 + 8 pad
#define SLAB_WORDS  (64 * SLAB_STRIDE)      // 8704 words per buffer
#define OFF_SLAB0   0
#define OFF_SLAB1   SLAB_WORDS              // 8704
#define OFF_ARGH    (2 * SLAB_WORDS)        // 17408: half2 words, stride 68
#define ARGH_STRIDE 68
#define OFF_FUNC    (OFF_ARGH + 128 * ARGH_STRIDE)  // 26112, f32, stride 36
#define FUNC_STRIDE 36
#define SM_WORDS    (OFF_FUNC + 128 * FUNC_STRIDE)  // 30720
#define SM_BYTES    (SM_WORDS * 4)          // 122880

// C packed fp16 j-pair-interleaved: g_CH[i][j2][z] = half2(C[i][2j2][z], C[i][2j2+1][z])
__device__ uint32_t g_CH[DV * 64 * DV];

__device__ __forceinline__ uint32_t smem_u32(const void* p) {
    uint32_t a;
    asm("{ .reg .u64 t; cvta.to.shared.u64 t, %1; cvt.u32.u64 %0, t; }"
        : "=r"(a) : "l"(p));
    return a;
}
__device__ __forceinline__ uint32_t pack_f16x2(float hi, float lo) {
    uint32_t r;
    asm("cvt.rn.f16x2.f32 %0, %1, %2;" : "=r"(r) : "f"(hi), "f"(lo));
    return r;
}
__device__ __forceinline__ uint32_t hmul2(uint32_t a, uint32_t b) {
    uint32_t r;
    asm("mul.rn.f16x2 %0, %1, %2;" : "=r"(r) : "r"(a), "r"(b));
    return r;
}
__device__ __forceinline__ void cp16(uint32_t dst, const void* src) {
    asm volatile("cp.async.cg.shared.global [%0], [%1], 16;"
                 :: "r"(dst), "l"(src) : "memory");
}
#define CP_COMMIT() asm volatile("cp.async.commit_group;" ::: "memory")
#define CP_WAIT(n)  asm volatile("cp.async.wait_group %0;" :: "n"(n) : "memory")

__device__ __forceinline__ void mma_f16(float* c, const uint32_t* a,
                                        uint32_t b0, uint32_t b1) {
    asm volatile(
        "mma.sync.aligned.m16n8k16.row.col.f32.f16.f16.f32 "
        "{%0,%1,%2,%3}, {%4,%5,%6,%7}, {%8,%9}, {%0,%1,%2,%3};"
        : "+f"(c[0]), "+f"(c[1]), "+f"(c[2]), "+f"(c[3])
        : "r"(a[0]), "r"(a[1]), "r"(a[2]), "r"(a[3]), "r"(b0), "r"(b1));
}

// ---- pack C -> fp16 pair-interleaved ----
__global__ void __launch_bounds__(256) pack_c(const float* __restrict__ C) {
    size_t idx = (size_t)blockIdx.x * 256 + threadIdx.x;   // 1,048,576
    int z  = (int)(idx & 127);
    int j2 = (int)((idx >> 7) & 63);
    int i  = (int)(idx >> 13);
    float v0 = C[((size_t)i * DV + 2 * j2) * DV + z];
    float v1 = C[((size_t)i * DV + 2 * j2 + 1) * DV + z];
    g_CH[idx] = pack_f16x2(v1, v0);
}

__global__ void __launch_bounds__(NT, 1)
cooc_mma(const float* __restrict__ fa, float* __restrict__ out) {
    extern __shared__ float sm[];
    const int tid  = threadIdx.x;
    const int warp = tid >> 5, lane = tid & 31;
    const int g = lane >> 2, q = lane & 3;
    const int mbase = (warp >> 1) * 32;   // warp-row tile (32 tokens)
    const int nbase = (warp & 1) * 64;    // warp-col tile (64 z)
    const int tok0 = blockIdx.x * 128;
    const int i0   = blockIdx.y * IPC;

    uint32_t* argh   = (uint32_t*)sm + OFF_ARGH;
    float*    func_sh = sm + OFF_FUNC;

    // ---- stage arg as half2 pairs [128 tok][64 j2] (stride 68 words) ----
    for (int idx = tid; idx < 128 * 32; idx += NT) {
        int t = idx >> 5, c4 = idx & 31;
        float4 v = *(const float4*)(fa + (size_t)(tok0 + t) * 256 + DV + c4 * 4);
        argh[t * ARGH_STRIDE + c4 * 2 + 0] = pack_f16x2(v.y, v.x);
        argh[t * ARGH_STRIDE + c4 * 2 + 1] = pack_f16x2(v.w, v.z);
    }
    // ---- func [128 tok][32 i] f32 (stride 36) ----
    for (int idx = tid; idx < 128 * 8; idx += NT) {
        int t = idx >> 3, c = idx & 7;
        float4 v = *(const float4*)(fa + (size_t)(tok0 + t) * 256 + i0 + c * 4);
        func_sh[t * FUNC_STRIDE + c * 4 + 0] = v.x;
        func_sh[t * FUNC_STRIDE + c * 4 + 1] = v.y;
        func_sh[t * FUNC_STRIDE + c * 4 + 2] = v.z;
        func_sh[t * FUNC_STRIDE + c * 4 + 3] = v.w;
    }

    // ---- cp.async slab stager: g_CH[i][64 j2][128 z] -> slab (stride 136 words)
    const uint32_t sb = smem_u32(sm);
    auto stage = [&](int i_rel, int buf) {
        const uint32_t* src = g_CH + ((size_t)(i0 + i_rel) << 13);
        uint32_t dstb = sb + (buf ? OFF_SLAB1 : OFF_SLAB0) * 4;
        #pragma unroll
        for (int k = 0; k < 8; k++) {
            int c = tid + k * NT;          // 16B chunk id, 0..2047
            int row = c >> 5, col = c & 31;
            cp16(dstb + (row * SLAB_STRIDE + col * 4) * 4,
                 src + row * 128 + col * 4);
        }
    };

    stage(0, 0);
    CP_COMMIT();

    float acc[2][8][4];
    #pragma unroll
    for (int mt = 0; mt < 2; mt++)
        #pragma unroll
        for (int nt = 0; nt < 8; nt++)
            #pragma unroll
            for (int k = 0; k < 4; k++) acc[mt][nt][k] = 0.f;

    uint32_t aF[2][2][4];    // [buf][mt][frag]
    uint32_t bF[2][8][2];    // [buf][nt][frag]

    for (int i = 0; i < IPC; i++) {
        if (i + 1 < IPC) { stage(i + 1, (i + 1) & 1); CP_COMMIT(); }
        if (i + 1 < IPC) CP_WAIT(1); else CP_WAIT(0);
        __syncthreads();

        const uint32_t* slab =
            (const uint32_t*)(sm + ((i & 1) ? OFF_SLAB1 : OFF_SLAB0));

        // func values for this i as broadcast half2: rows mbase + g + 8s
        uint32_t fr2[4];
        #pragma unroll
        for (int s = 0; s < 4; s++) {
            float fv = func_sh[(mbase + g + 8 * s) * FUNC_STRIDE + i];
            fr2[s] = pack_f16x2(fv, fv);
        }

        // fragment loader for k16-chunk c into buffer fb
        auto load_chunk = [&](int c, int fb) {
            const int c8 = c * 8;       // j2 base
            #pragma unroll
            for (int nt = 0; nt < 8; nt++) {
                const uint32_t* bp =
                    slab + (c8 + q) * SLAB_STRIDE + nbase + nt * 8 + g;
                bF[fb][nt][0] = bp[0];
                bF[fb][nt][1] = bp[4 * SLAB_STRIDE];
            }
            #pragma unroll
            for (int s = 0; s < 4; s++) {
                const uint32_t* ap =
                    argh + (mbase + g + 8 * s) * ARGH_STRIDE + c8 + q;
                uint32_t alo = hmul2(fr2[s], ap[0]);   // k = 2q, 2q+1
                uint32_t ahi = hmul2(fr2[s], ap[4]);   // k = 2q+8, 2q+9
                aF[fb][s >> 1][(s & 1) ? 1 : 0] = alo;
                aF[fb][s >> 1][(s & 1) ? 3 : 2] = ahi;
            }
        };

        load_chunk(0, 0);
        #pragma unroll
        for (int c = 0; c < 8; c++) {
            const int cur = c & 1, nxt = cur ^ 1;
            if (c < 7) load_chunk(c + 1, nxt);
            #pragma unroll
            for (int nt = 0; nt < 8; nt++) {
                mma_f16(acc[0][nt], aF[cur][0], bF[cur][nt][0], bF[cur][nt][1]);
                mma_f16(acc[1][nt], aF[cur][1], bF[cur][nt][0], bF[cur][nt][1]);
            }
        }
        __syncthreads();
    }

    // ---- epilogue: KSPLIT deterministic partials via atomicAdd over zeroed out
    #pragma unroll
    for (int mt = 0; mt < 2; mt++) {
        int r0 = tok0 + mbase + mt * 16 + g;
        #pragma unroll
        for (int nt = 0; nt < 8; nt++) {
            int col = nbase + nt * 8 + 2 * q;
            float* p0 = out + (size_t)r0 * DV + col;
            atomicAdd(p0,              acc[mt][nt][0]);
            atomicAdd(p0 + 1,          acc[mt][nt][1]);
            atomicAdd(p0 + 8 * DV,     acc[mt][nt][2]);
            atomicAdd(p0 + 8 * DV + 1, acc[mt][nt][3]);
        }
    }
}

extern "C" void kernel_launch(void* const* d_in, const int* in_sizes, int n_in,
                              void* d_out, int out_size) {
    const float* fa = (const float*)d_in[0];   // (4,1024,256)
    const float* Cm = (const float*)d_in[1];   // (128,128,128)
    if (n_in >= 2 && in_sizes[0] > in_sizes[1]) {
        const float* t = fa; fa = Cm; Cm = t;
    }
    float* out = (float*)d_out;

    cudaFuncSetAttribute(cooc_mma, cudaFuncAttributeMaxDynamicSharedMemorySize,
                         SM_BYTES);
    cudaMemsetAsync(d_out, 0, (size_t)out_size * sizeof(float));
    pack_c<<<4096, 256>>>(Cm);
    cooc_mma<<<dim3(4096 / 128, KSPLIT), NT, SM_BYTES>>>(fa, out);
}

// round 8
// speedup vs baseline: 6.0492x; 1.0476x over previous
#include <cuda_runtime.h>
#include <cuda_fp16.h>
#include <cstdint>

#define DV 128
#define NT 256
#define NWORK 4096      // 32 token-tiles * 128 i-values

// smem word-offsets (32-bit words)
#define SLAB_STRIDE 136                     // words (half2) per j2-row: 128 + 8 pad
#define SLAB_WORDS  (64 * SLAB_STRIDE)      // 8704 words per buffer
#define OFF_SLAB0   0
#define OFF_SLAB1   SLAB_WORDS              // 8704
#define OFF_ARGH    (2 * SLAB_WORDS)        // 17408: half2 words, stride 68
#define ARGH_STRIDE 68
#define SM_WORDS    (OFF_ARGH + 128 * ARGH_STRIDE)  // 26112
#define SM_BYTES    (SM_WORDS * 4)          // 104448

// C packed fp16 j-pair-interleaved: g_CH[i][j2][z] = half2(C[i][2j2][z], C[i][2j2+1][z])
__device__ uint32_t g_CH[DV * 64 * DV];

__device__ __forceinline__ uint32_t smem_u32(const void* p) {
    uint32_t a;
    asm("{ .reg .u64 t; cvta.to.shared.u64 t, %1; cvt.u32.u64 %0, t; }"
        : "=r"(a) : "l"(p));
    return a;
}
__device__ __forceinline__ uint32_t pack_f16x2(float hi, float lo) {
    uint32_t r;
    asm("cvt.rn.f16x2.f32 %0, %1, %2;" : "=r"(r) : "f"(hi), "f"(lo));
    return r;
}
__device__ __forceinline__ uint32_t hmul2(uint32_t a, uint32_t b) {
    uint32_t r;
    asm("mul.rn.f16x2 %0, %1, %2;" : "=r"(r) : "r"(a), "r"(b));
    return r;
}
__device__ __forceinline__ void cp16(uint32_t dst, const void* src) {
    asm volatile("cp.async.cg.shared.global [%0], [%1], 16;"
                 :: "r"(dst), "l"(src) : "memory");
}
#define CP_COMMIT() asm volatile("cp.async.commit_group;" ::: "memory")
#define CP_WAIT(n)  asm volatile("cp.async.wait_group %0;" :: "n"(n) : "memory")

__device__ __forceinline__ void mma_f16(float* c, const uint32_t* a,
                                        uint32_t b0, uint32_t b1) {
    asm volatile(
        "mma.sync.aligned.m16n8k16.row.col.f32.f16.f16.f32 "
        "{%0,%1,%2,%3}, {%4,%5,%6,%7}, {%8,%9}, {%0,%1,%2,%3};"
        : "+f"(c[0]), "+f"(c[1]), "+f"(c[2]), "+f"(c[3])
        : "r"(a[0]), "r"(a[1]), "r"(a[2]), "r"(a[3]), "r"(b0), "r"(b1));
}

// ---- pack C -> fp16 pair-interleaved ----
__global__ void __launch_bounds__(256) pack_c(const float* __restrict__ C) {
    size_t idx = (size_t)blockIdx.x * 256 + threadIdx.x;   // 1,048,576
    int z  = (int)(idx & 127);
    int j2 = (int)((idx >> 7) & 63);
    int i  = (int)(idx >> 13);
    float v0 = C[((size_t)i * DV + 2 * j2) * DV + z];
    float v1 = C[((size_t)i * DV + 2 * j2 + 1) * DV + z];
    g_CH[idx] = pack_f16x2(v1, v0);
}

__global__ void __launch_bounds__(NT, 1)
cooc_mma(const float* __restrict__ fa, float* __restrict__ out) {
    extern __shared__ float sm[];
    const int tid  = threadIdx.x;
    const int warp = tid >> 5, lane = tid & 31;
    const int g = lane >> 2, q = lane & 3;
    const int mbase = (warp >> 1) * 32;   // warp-row tile (32 tokens)
    const int nbase = (warp & 1) * 64;    // warp-col tile (64 z)

    uint32_t* argh = (uint32_t*)sm + OFF_ARGH;
    const uint32_t sb = smem_u32(sm);

    // stream-K range for this CTA
    const unsigned nb = gridDim.x;
    const unsigned w0 = (unsigned)((unsigned long long)blockIdx.x * NWORK / nb);
    const unsigned w1 = (unsigned)((unsigned long long)(blockIdx.x + 1) * NWORK / nb);

    // ---- arg restage (direct LDG -> half2 STS), tile t ----
    auto stage_arg = [&](int tile) {
        const int tok0 = tile * 128;
        #pragma unroll 4
        for (int idx = tid; idx < 128 * 32; idx += NT) {
            int t = idx >> 5, c4 = idx & 31;
            float4 v = *(const float4*)(fa + (size_t)(tok0 + t) * 256 + DV + c4 * 4);
            argh[t * ARGH_STRIDE + c4 * 2 + 0] = pack_f16x2(v.y, v.x);
            argh[t * ARGH_STRIDE + c4 * 2 + 1] = pack_f16x2(v.w, v.z);
        }
    };
    // ---- cp.async slab stager: g_CH[i][64 j2][128 z] -> slab ----
    auto stage_slab = [&](int i, int buf) {
        const uint32_t* src = g_CH + ((size_t)i << 13);
        uint32_t dstb = sb + (buf ? OFF_SLAB1 : OFF_SLAB0) * 4;
        #pragma unroll
        for (int k = 0; k < 8; k++) {
            int c = tid + k * NT;          // 16B chunk id, 0..2047
            int row = c >> 5, col = c & 31;
            cp16(dstb + (row * SLAB_STRIDE + col * 4) * 4,
                 src + row * 128 + col * 4);
        }
    };
    // ---- func column prefetch for work unit w (4 regs) ----
    auto load_func = [&](unsigned w, float* fr) {
        const int tk = (int)(w >> 7) * 128;
        const int i  = (int)(w & 127);
        #pragma unroll
        for (int s = 0; s < 4; s++)
            fr[s] = fa[(size_t)(tk + mbase + g + 8 * s) * 256 + i];
    };

    float acc[2][8][4];
    #pragma unroll
    for (int mt = 0; mt < 2; mt++)
        #pragma unroll
        for (int nt = 0; nt < 8; nt++)
            #pragma unroll
            for (int k = 0; k < 4; k++) acc[mt][nt][k] = 0.f;

    auto flush = [&](int tile) {
        const int tok0 = tile * 128;
        #pragma unroll
        for (int mt = 0; mt < 2; mt++) {
            int r0 = tok0 + mbase + mt * 16 + g;
            #pragma unroll
            for (int nt = 0; nt < 8; nt++) {
                int col = nbase + nt * 8 + 2 * q;
                float* p0 = out + (size_t)r0 * DV + col;
                atomicAdd(p0,              acc[mt][nt][0]);
                atomicAdd(p0 + 1,          acc[mt][nt][1]);
                atomicAdd(p0 + 8 * DV,     acc[mt][nt][2]);
                atomicAdd(p0 + 8 * DV + 1, acc[mt][nt][3]);
                acc[mt][nt][0] = acc[mt][nt][1] = 0.f;
                acc[mt][nt][2] = acc[mt][nt][3] = 0.f;
            }
        }
    };

    int cur_tile = (int)(w0 >> 7);
    stage_arg(cur_tile);
    stage_slab((int)(w0 & 127), 0);
    CP_COMMIT();
    float fr_next[4];
    load_func(w0, fr_next);

    uint32_t aF[2][2][4];    // [buf][mt][frag]
    uint32_t bF[2][8][2];    // [buf][nt][frag]

    for (unsigned w = w0; w < w1; ++w) {
        const int buf = (int)((w - w0) & 1);
        const int tile = (int)(w >> 7);
        if (tile != cur_tile) {      // uniform across CTA; prev iter ended in sync
            flush(cur_tile);
            cur_tile = tile;
            stage_arg(cur_tile);     // visibility via the barrier below
        }
        if (w + 1 < w1) { stage_slab((int)((w + 1) & 127), buf ^ 1); CP_COMMIT(); }

        float fr_cur[4];
        #pragma unroll
        for (int s = 0; s < 4; s++) fr_cur[s] = fr_next[s];
        if (w + 1 < w1) load_func(w + 1, fr_next);

        if (w + 1 < w1) CP_WAIT(1); else CP_WAIT(0);
        __syncthreads();

        const uint32_t* slab =
            (const uint32_t*)(sm + (buf ? OFF_SLAB1 : OFF_SLAB0));

        uint32_t fr2[4];
        #pragma unroll
        for (int s = 0; s < 4; s++) fr2[s] = pack_f16x2(fr_cur[s], fr_cur[s]);

        auto load_chunk = [&](int c, int fb) {
            const int c8 = c * 8;       // j2 base
            #pragma unroll
            for (int nt = 0; nt < 8; nt++) {
                const uint32_t* bp =
                    slab + (c8 + q) * SLAB_STRIDE + nbase + nt * 8 + g;
                bF[fb][nt][0] = bp[0];
                bF[fb][nt][1] = bp[4 * SLAB_STRIDE];
            }
            #pragma unroll
            for (int s = 0; s < 4; s++) {
                const uint32_t* ap =
                    argh + (mbase + g + 8 * s) * ARGH_STRIDE + c8 + q;
                uint32_t alo = hmul2(fr2[s], ap[0]);   // k = 2q, 2q+1
                uint32_t ahi = hmul2(fr2[s], ap[4]);   // k = 2q+8, 2q+9
                aF[fb][s >> 1][(s & 1) ? 1 : 0] = alo;
                aF[fb][s >> 1][(s & 1) ? 3 : 2] = ahi;
            }
        };

        load_chunk(0, 0);
        #pragma unroll
        for (int c = 0; c < 8; c++) {
            const int cur = c & 1, nxt = cur ^ 1;
            if (c < 7) load_chunk(c + 1, nxt);
            #pragma unroll
            for (int nt = 0; nt < 8; nt++) {
                mma_f16(acc[0][nt], aF[cur][0], bF[cur][nt][0], bF[cur][nt][1]);
                mma_f16(acc[1][nt], aF[cur][1], bF[cur][nt][0], bF[cur][nt][1]);
            }
        }
        __syncthreads();
    }
    flush(cur_tile);
}

extern "C" void kernel_launch(void* const* d_in, const int* in_sizes, int n_in,
                              void* d_out, int out_size) {
    const float* fa = (const float*)d_in[0];   // (4,1024,256)
    const float* Cm = (const float*)d_in[1];   // (128,128,128)
    if (n_in >= 2 && in_sizes[0] > in_sizes[1]) {
        const float* t = fa; fa = Cm; Cm = t;
    }
    float* out = (float*)d_out;

    int nsm = 148;
    cudaDeviceGetAttribute(&nsm, cudaDevAttrMultiProcessorCount, 0);
    if (nsm <= 0 || nsm > NWORK) nsm = 148;

    cudaFuncSetAttribute(cooc_mma, cudaFuncAttributeMaxDynamicSharedMemorySize,
                         SM_BYTES);
    cudaMemsetAsync(d_out, 0, (size_t)out_size * sizeof(float));
    pack_c<<<4096, 256>>>(Cm);
    cooc_mma<<<nsm, NT, SM_BYTES>>>(fa, out);
}

// round 9
// speedup vs baseline: 6.3940x; 1.0570x over previous
#include <cuda_runtime.h>
#include <cuda_fp16.h>
#include <cstdint>

#define DV 128
#define NT 256
#define NWORK 4096      // 32 token-tiles * 128 i-values

// smem offsets in uint2 units
#define SLAB_STRIDE 132                 // uint2 per (c,q)-row: 128 + 4 pad
#define SLAB_U2     (32 * SLAB_STRIDE)  // 4224 uint2 per buffer
#define OFF_SLAB0   0
#define OFF_SLAB1   SLAB_U2             // 4224
#define OFF_ARGP    (2 * SLAB_U2)       // 8448
#define ARGP_STRIDE 36                  // uint2 per token row: 32 + 4 pad
#define SM_U2       (OFF_ARGP + 128 * ARGP_STRIDE)  // 13056
#define SM_BYTES    (SM_U2 * 8)         // 104448

// C pair-packed: g_CP[i*4096 + c*512 + q*128 + z] =
//   { half2(C[i][16c+2q][z],   C[i][16c+2q+1][z]),
//     half2(C[i][16c+2q+8][z], C[i][16c+2q+9][z]) }
__device__ uint2 g_CP[DV * 4096];

__device__ __forceinline__ uint32_t smem_u32(const void* p) {
    uint32_t a;
    asm("{ .reg .u64 t; cvta.to.shared.u64 t, %1; cvt.u32.u64 %0, t; }"
        : "=r"(a) : "l"(p));
    return a;
}
__device__ __forceinline__ uint32_t pack_f16x2(float hi, float lo) {
    uint32_t r;
    asm("cvt.rn.f16x2.f32 %0, %1, %2;" : "=r"(r) : "f"(hi), "f"(lo));
    return r;
}
__device__ __forceinline__ uint32_t hmul2(uint32_t a, uint32_t b) {
    uint32_t r;
    asm("mul.rn.f16x2 %0, %1, %2;" : "=r"(r) : "r"(a), "r"(b));
    return r;
}
__device__ __forceinline__ void cp16(uint32_t dst, const void* src) {
    asm volatile("cp.async.cg.shared.global [%0], [%1], 16;"
                 :: "r"(dst), "l"(src) : "memory");
}
#define CP_COMMIT() asm volatile("cp.async.commit_group;" ::: "memory")
#define CP_WAIT(n)  asm volatile("cp.async.wait_group %0;" :: "n"(n) : "memory")

__device__ __forceinline__ void mma_f16(float* c, const uint32_t* a,
                                        uint32_t b0, uint32_t b1) {
    asm volatile(
        "mma.sync.aligned.m16n8k16.row.col.f32.f16.f16.f32 "
        "{%0,%1,%2,%3}, {%4,%5,%6,%7}, {%8,%9}, {%0,%1,%2,%3};"
        : "+f"(c[0]), "+f"(c[1]), "+f"(c[2]), "+f"(c[3])
        : "r"(a[0]), "r"(a[1]), "r"(a[2]), "r"(a[3]), "r"(b0), "r"(b1));
}

// ---- pack C -> fp16 pair-of-pairs layout; also zero the output ----
__global__ void __launch_bounds__(256) pack_c(const float* __restrict__ C,
                                              float* __restrict__ out) {
    unsigned idx = blockIdx.x * 256 + threadIdx.x;   // 524288 threads
    out[idx] = 0.f;                                  // out has 524288 floats
    int z = (int)(idx & 127);
    int q = (int)((idx >> 7) & 3);
    int c = (int)((idx >> 9) & 7);
    int i = (int)(idx >> 12);
    const float* base = C + ((size_t)i * DV + 16 * c + 2 * q) * DV + z;
    float v0 = base[0];
    float v1 = base[DV];
    float v8 = base[8 * DV];
    float v9 = base[9 * DV];
    uint2 r;
    r.x = pack_f16x2(v1, v0);
    r.y = pack_f16x2(v9, v8);
    g_CP[idx] = r;
}

__global__ void __launch_bounds__(NT, 1)
cooc_mma(const float* __restrict__ fa, float* __restrict__ out) {
    extern __shared__ uint2 smu[];
    const int tid  = threadIdx.x;
    const int warp = tid >> 5, lane = tid & 31;
    const int g = lane >> 2, q = lane & 3;
    const int mbase = (warp >> 1) * 32;   // warp-row tile (32 tokens)
    const int nbase = (warp & 1) * 64;    // warp-col tile (64 z)

    uint2* argp = smu + OFF_ARGP;
    uint32_t* arg32 = (uint32_t*)argp;
    const uint32_t sb = smem_u32(smu);

    // stream-K range for this CTA
    const unsigned nb = gridDim.x;
    const unsigned w0 = (unsigned)((unsigned long long)blockIdx.x * NWORK / nb);
    const unsigned w1 = (unsigned)((unsigned long long)(blockIdx.x + 1) * NWORK / nb);

    // ---- arg restage: f32 LDG -> pair-packed half2 uint2 [t][c*4+q] ----
    auto stage_arg = [&](int tile) {
        const int tok0 = tile * 128;
        #pragma unroll 4
        for (int idx = tid; idx < 128 * 32; idx += NT) {
            int t = idx >> 5, c4 = idx & 31;
            float4 v = *(const float4*)(fa + (size_t)(tok0 + t) * 256 + DV + c4 * 4);
            int cc = c4 >> 2;            // chunk
            int ra = (2 * c4) & 7;       // r of first j2
            uint32_t w0v = pack_f16x2(v.y, v.x);
            uint32_t w1v = pack_f16x2(v.w, v.z);
            int ia = 2 * (t * ARGP_STRIDE + cc * 4 + (ra & 3)) + (ra >> 2);
            int rb = ra + 1;
            int ib = 2 * (t * ARGP_STRIDE + cc * 4 + (rb & 3)) + (rb >> 2);
            arg32[ia] = w0v;
            arg32[ib] = w1v;
        }
    };
    // ---- cp.async slab stager: g_CP[i] (32 rows x 128 uint2) -> slab ----
    auto stage_slab = [&](int i, int buf) {
        const uint2* src = g_CP + ((size_t)i << 12);
        uint32_t dstb = sb + (buf ? OFF_SLAB1 : OFF_SLAB0) * 8;
        #pragma unroll
        for (int k = 0; k < 8; k++) {
            int c = tid + k * NT;          // 16B chunk id, 0..2047
            int row = c >> 6, col = c & 63;
            cp16(dstb + (row * SLAB_STRIDE + col * 2) * 8,
                 src + row * 128 + col * 2);
        }
    };
    // ---- func column prefetch for work unit w (4 regs) ----
    auto load_func = [&](unsigned w, float* fr) {
        const int tk = (int)(w >> 7) * 128;
        const int i  = (int)(w & 127);
        #pragma unroll
        for (int s = 0; s < 4; s++)
            fr[s] = fa[(size_t)(tk + mbase + g + 8 * s) * 256 + i];
    };

    float acc[2][8][4];
    #pragma unroll
    for (int mt = 0; mt < 2; mt++)
        #pragma unroll
        for (int nt = 0; nt < 8; nt++)
            #pragma unroll
            for (int k = 0; k < 4; k++) acc[mt][nt][k] = 0.f;

    auto flush = [&](int tile) {
        const int tok0 = tile * 128;
        #pragma unroll
        for (int mt = 0; mt < 2; mt++) {
            int r0 = tok0 + mbase + mt * 16 + g;
            #pragma unroll
            for (int nt = 0; nt < 8; nt++) {
                int col = nbase + nt * 8 + 2 * q;
                float* p0 = out + (size_t)r0 * DV + col;
                atomicAdd(p0,              acc[mt][nt][0]);
                atomicAdd(p0 + 1,          acc[mt][nt][1]);
                atomicAdd(p0 + 8 * DV,     acc[mt][nt][2]);
                atomicAdd(p0 + 8 * DV + 1, acc[mt][nt][3]);
                acc[mt][nt][0] = acc[mt][nt][1] = 0.f;
                acc[mt][nt][2] = acc[mt][nt][3] = 0.f;
            }
        }
    };

    int cur_tile = (int)(w0 >> 7);
    stage_arg(cur_tile);
    stage_slab((int)(w0 & 127), 0);
    CP_COMMIT();
    float fr_next[4];
    load_func(w0, fr_next);

    uint32_t aF[2][2][4];    // [buf][mt][frag]
    uint32_t bF[2][8][2];    // [buf][nt][frag]

    for (unsigned w = w0; w < w1; ++w) {
        const int buf = (int)((w - w0) & 1);
        const int tile = (int)(w >> 7);
        if (tile != cur_tile) {      // uniform across CTA; prev iter ended in sync
            flush(cur_tile);
            cur_tile = tile;
            stage_arg(cur_tile);
        }
        if (w + 1 < w1) { stage_slab((int)((w + 1) & 127), buf ^ 1); CP_COMMIT(); }

        float fr_cur[4];
        #pragma unroll
        for (int s = 0; s < 4; s++) fr_cur[s] = fr_next[s];
        if (w + 1 < w1) load_func(w + 1, fr_next);

        if (w + 1 < w1) CP_WAIT(1); else CP_WAIT(0);
        __syncthreads();

        const uint2* slab = smu + (buf ? OFF_SLAB1 : OFF_SLAB0);

        uint32_t fr2[4];
        #pragma unroll
        for (int s = 0; s < 4; s++) fr2[s] = pack_f16x2(fr_cur[s], fr_cur[s]);

        // fragment loader for k16-chunk c into buffer fb (all LDS.64)
        auto load_chunk = [&](int c, int fb) {
            const uint2* brow = slab + (c * 4 + q) * SLAB_STRIDE + nbase + g;
            #pragma unroll
            for (int nt = 0; nt < 8; nt++) {
                uint2 v = brow[nt * 8];
                bF[fb][nt][0] = v.x;
                bF[fb][nt][1] = v.y;
            }
            #pragma unroll
            for (int s = 0; s < 4; s++) {
                uint2 av = argp[(mbase + g + 8 * s) * ARGP_STRIDE + c * 4 + q];
                aF[fb][s >> 1][(s & 1) ? 1 : 0] = hmul2(fr2[s], av.x);
                aF[fb][s >> 1][(s & 1) ? 3 : 2] = hmul2(fr2[s], av.y);
            }
        };

        load_chunk(0, 0);
        #pragma unroll
        for (int c = 0; c < 8; c++) {
            const int cur = c & 1, nxt = cur ^ 1;
            if (c < 7) load_chunk(c + 1, nxt);
            #pragma unroll
            for (int nt = 0; nt < 8; nt++) {
                mma_f16(acc[0][nt], aF[cur][0], bF[cur][nt][0], bF[cur][nt][1]);
                mma_f16(acc[1][nt], aF[cur][1], bF[cur][nt][0], bF[cur][nt][1]);
            }
        }
        __syncthreads();
    }
    flush(cur_tile);
}

extern "C" void kernel_launch(void* const* d_in, const int* in_sizes, int n_in,
                              void* d_out, int out_size) {
    const float* fa = (const float*)d_in[0];   // (4,1024,256)
    const float* Cm = (const float*)d_in[1];   // (128,128,128)
    if (n_in >= 2 && in_sizes[0] > in_sizes[1]) {
        const float* t = fa; fa = Cm; Cm = t;
    }
    float* out = (float*)d_out;

    int nsm = 148;
    cudaDeviceGetAttribute(&nsm, cudaDevAttrMultiProcessorCount, 0);
    if (nsm <= 0 || nsm > NWORK) nsm = 148;

    cudaFuncSetAttribute(cooc_mma, cudaFuncAttributeMaxDynamicSharedMemorySize,
                         SM_BYTES);
    pack_c<<<2048, 256>>>(Cm, out);   // also zeroes out
    cooc_mma<<<nsm, NT, SM_BYTES>>>(fa, out);
}